// round 3
// baseline (speedup 1.0000x reference)
#include <cuda_runtime.h>
#include <math_constants.h>

// Per-batch log-likelihood scratch (allocation-free; 4096 >= B=512 with headroom).
__device__ float g_ll[4096];

#define KC 4  // n_center (fixed by problem)

__global__ void __launch_bounds__(128) ll_kernel(
    const float* __restrict__ x,
    const int* __restrict__ y,
    const float* __restrict__ mu_base,
    const float* __restrict__ cmu,
    const float* __restrict__ csig,
    const float* __restrict__ cpi,
    int H)
{
    const int b    = blockIdx.x;
    const int tid  = threadIdx.x;
    const int lane = tid & 31;
    const int warp = tid >> 5;
    const int cls  = y[b];
    const float inv_g = 0.1f;  // 1 / GAMA

    const int H4 = H >> 2;
    const float4* __restrict__ x4  = reinterpret_cast<const float4*>(x) + (size_t)b * H4;
    const float4* __restrict__ mb4 = reinterpret_cast<const float4*>(mu_base);
    const float4* __restrict__ mu0 = reinterpret_cast<const float4*>(cmu)  + (size_t)cls * KC * H4;
    const float4* __restrict__ sg0 = reinterpret_cast<const float4*>(csig) + (size_t)cls * KC * H4;

    float acc[KC];
#pragma unroll
    for (int k = 0; k < KC; ++k) acc[k] = 0.0f;

    for (int i = tid; i < H4; i += blockDim.x) {
        float4 xv = x4[i];
        float4 mv = mb4[i];
        float xs0 = (xv.x - mv.x) * inv_g;
        float xs1 = (xv.y - mv.y) * inv_g;
        float xs2 = (xv.z - mv.z) * inv_g;
        float xs3 = (xv.w - mv.w) * inv_g;
#pragma unroll
        for (int k = 0; k < KC; ++k) {
            float4 m = mu0[k * H4 + i];
            float4 s = sg0[k * H4 + i];
            float d0 = xs0 - m.x;
            float d1 = xs1 - m.y;
            float d2 = xs2 - m.z;
            float d3 = xs3 - m.w;
            float t;
            t  = __logf(s.x) - 0.5f * d0 * d0 * s.x * s.x;
            t += __logf(s.y) - 0.5f * d1 * d1 * s.y * s.y;
            t += __logf(s.z) - 0.5f * d2 * d2 * s.z * s.z;
            t += __logf(s.w) - 0.5f * d3 * d3 * s.w * s.w;
            acc[k] += t;
        }
    }

    // Warp butterfly reduction of the 4 per-center partial sums.
#pragma unroll
    for (int o = 16; o > 0; o >>= 1) {
#pragma unroll
        for (int k = 0; k < KC; ++k)
            acc[k] += __shfl_xor_sync(0xFFFFFFFFu, acc[k], o);
    }

    __shared__ float sp[4][KC];  // up to 4 warps at 128 threads
    if (lane == 0) {
#pragma unroll
        for (int k = 0; k < KC; ++k) sp[warp][k] = acc[k];
    }
    __syncthreads();

    if (tid == 0) {
        const int nw = blockDim.x >> 5;
        float tot[KC];
#pragma unroll
        for (int k = 0; k < KC; ++k) {
            float t = 0.0f;
            for (int w = 0; w < nw; ++w) t += sp[w][k];
            tot[k] = t;
        }
        // log-softmax over class_pi[cls, :]
        float pi[KC];
        float pmax = -CUDART_INF_F;
#pragma unroll
        for (int k = 0; k < KC; ++k) {
            pi[k] = cpi[cls * KC + k];
            pmax = fmaxf(pmax, pi[k]);
        }
        float se = 0.0f;
#pragma unroll
        for (int k = 0; k < KC; ++k) se += __expf(pi[k] - pmax);
        const float lse = __logf(se) + pmax;

        const float cst = -0.5f * (float)H * 1.8378770664093453f;  // log(2*pi)
        float best = -CUDART_INF_F;
#pragma unroll
        for (int k = 0; k < KC; ++k)
            best = fmaxf(best, tot[k] + cst + pi[k] - lse);
        g_ll[b] = best;
    }
}

__global__ void __launch_bounds__(512) reduce_kernel(float* __restrict__ out, int B)
{
    __shared__ float s[512];
    const int tid = threadIdx.x;
    float v = 0.0f;
    for (int i = tid; i < B; i += blockDim.x) v += g_ll[i];
    s[tid] = v;
    __syncthreads();
    for (int o = blockDim.x >> 1; o > 0; o >>= 1) {
        if (tid < o) s[tid] += s[tid + o];
        __syncthreads();
    }
    if (tid == 0) out[0] = s[0] / (float)B;
}

extern "C" void kernel_launch(void* const* d_in, const int* in_sizes, int n_in,
                              void* d_out, int out_size)
{
    const float* x   = (const float*)d_in[0];
    const int*   y   = (const int*)d_in[1];
    const float* mub = (const float*)d_in[2];
    const float* cmu = (const float*)d_in[3];
    const float* csg = (const float*)d_in[4];
    const float* cpi = (const float*)d_in[5];
    float*       out = (float*)d_out;

    const int B = in_sizes[1];  // batch (y elements)
    const int H = in_sizes[2];  // hidden (mu_base elements)

    ll_kernel<<<B, 128>>>(x, y, mub, cmu, csg, cpi, H);
    reduce_kernel<<<1, 512>>>(out, B);
}

// round 4
// speedup vs baseline: 1.1536x; 1.1536x over previous
#include <cuda_runtime.h>
#include <math_constants.h>

// Allocation-free scratch. g_ll holds per-batch log-likelihoods; g_cnt is the
// last-block ticket, reset to 0 by the last block itself (replay-safe).
__device__ float g_ll[4096];
__device__ unsigned int g_cnt = 0;

#define KC 4  // n_center (fixed by problem)

__global__ void __launch_bounds__(128) ll_fused_kernel(
    const float* __restrict__ x,
    const int* __restrict__ y,
    const float* __restrict__ mu_base,
    const float* __restrict__ cmu,
    const float* __restrict__ csig,
    const float* __restrict__ cpi,
    float* __restrict__ out,
    int H, int B)
{
    const int b    = blockIdx.x;
    const int tid  = threadIdx.x;
    const int lane = tid & 31;
    const int warp = tid >> 5;
    const int cls  = y[b];          // first: everything gathered depends on it
    const float inv_g = 0.1f;       // 1 / GAMA

    const int H4 = H >> 2;
    const float4* __restrict__ x4  = reinterpret_cast<const float4*>(x) + (size_t)b * H4;
    const float4* __restrict__ mb4 = reinterpret_cast<const float4*>(mu_base);
    const float4* __restrict__ mu0 = reinterpret_cast<const float4*>(cmu)  + (size_t)cls * KC * H4;
    const float4* __restrict__ sg0 = reinterpret_cast<const float4*>(csig) + (size_t)cls * KC * H4;

    float acc[KC];
#pragma unroll
    for (int k = 0; k < KC; ++k) acc[k] = 0.0f;

    for (int i = tid; i < H4; i += blockDim.x) {
        float4 xv = x4[i];
        float4 mv = mb4[i];
        float xs0 = (xv.x - mv.x) * inv_g;
        float xs1 = (xv.y - mv.y) * inv_g;
        float xs2 = (xv.z - mv.z) * inv_g;
        float xs3 = (xv.w - mv.w) * inv_g;
#pragma unroll
        for (int k = 0; k < KC; ++k) {
            float4 m = mu0[k * H4 + i];
            float4 s = sg0[k * H4 + i];
            float d0 = xs0 - m.x;
            float d1 = xs1 - m.y;
            float d2 = xs2 - m.z;
            float d3 = xs3 - m.w;
            float t;
            t  = __logf(s.x) - 0.5f * d0 * d0 * s.x * s.x;
            t += __logf(s.y) - 0.5f * d1 * d1 * s.y * s.y;
            t += __logf(s.z) - 0.5f * d2 * d2 * s.z * s.z;
            t += __logf(s.w) - 0.5f * d3 * d3 * s.w * s.w;
            acc[k] += t;
        }
    }

    // Warp butterfly reduction of the 4 per-center partial sums.
#pragma unroll
    for (int o = 16; o > 0; o >>= 1) {
#pragma unroll
        for (int k = 0; k < KC; ++k)
            acc[k] += __shfl_xor_sync(0xFFFFFFFFu, acc[k], o);
    }

    __shared__ float sp[4][KC];
    __shared__ bool s_last;
    if (lane == 0) {
#pragma unroll
        for (int k = 0; k < KC; ++k) sp[warp][k] = acc[k];
    }
    __syncthreads();

    if (tid == 0) {
        const int nw = blockDim.x >> 5;
        float tot[KC];
#pragma unroll
        for (int k = 0; k < KC; ++k) {
            float t = 0.0f;
            for (int w = 0; w < nw; ++w) t += sp[w][k];
            tot[k] = t;
        }
        // log-softmax over class_pi[cls, :]
        float pi[KC];
        float pmax = -CUDART_INF_F;
#pragma unroll
        for (int k = 0; k < KC; ++k) {
            pi[k] = cpi[cls * KC + k];
            pmax = fmaxf(pmax, pi[k]);
        }
        float se = 0.0f;
#pragma unroll
        for (int k = 0; k < KC; ++k) se += __expf(pi[k] - pmax);
        const float lse = __logf(se) + pmax;

        const float cst = -0.5f * (float)H * 1.8378770664093453f;  // log(2*pi)
        float best = -CUDART_INF_F;
#pragma unroll
        for (int k = 0; k < KC; ++k)
            best = fmaxf(best, tot[k] + cst + pi[k] - lse);
        g_ll[b] = best;

        // Publish, then take a ticket. The block drawing the last ticket
        // performs the final deterministic reduction.
        __threadfence();
        unsigned int ticket = atomicAdd(&g_cnt, 1u);
        s_last = (ticket == (unsigned int)(gridDim.x - 1));
    }
    __syncthreads();

    if (s_last) {
        // Fixed-order tree reduction of B values with 128 threads.
        __shared__ float sr[128];
        float v = 0.0f;
        for (int i = tid; i < B; i += 128) v += g_ll[i];
        sr[tid] = v;
        __syncthreads();
#pragma unroll
        for (int o = 64; o > 32; o >>= 1) {
            if (tid < o) sr[tid] += sr[tid + o];
            __syncthreads();
        }
        if (tid < 32) {
            float w = sr[tid] + sr[tid + 32];
#pragma unroll
            for (int o = 16; o > 0; o >>= 1)
                w += __shfl_xor_sync(0xFFFFFFFFu, w, o);
            if (tid == 0) {
                out[0] = w / (float)B;
                g_cnt = 0;  // reset for next graph replay
            }
        }
    }
}

extern "C" void kernel_launch(void* const* d_in, const int* in_sizes, int n_in,
                              void* d_out, int out_size)
{
    const float* x   = (const float*)d_in[0];
    const int*   y   = (const int*)d_in[1];
    const float* mub = (const float*)d_in[2];
    const float* cmu = (const float*)d_in[3];
    const float* csg = (const float*)d_in[4];
    const float* cpi = (const float*)d_in[5];
    float*       out = (float*)d_out;

    const int B = in_sizes[1];  // batch (y elements)
    const int H = in_sizes[2];  // hidden (mu_base elements)

    ll_fused_kernel<<<B, 128>>>(x, y, mub, cmu, csg, cpi, out, H, B);
}

// round 5
// speedup vs baseline: 1.1577x; 1.0036x over previous
#include <cuda_runtime.h>
#include <math_constants.h>

// Allocation-free scratch. g_ll holds per-batch log-likelihoods; g_cnt is the
// last-block ticket, reset to 0 by the last block itself (replay-safe).
__device__ float g_ll[4096];
__device__ unsigned int g_cnt = 0;

#define KC 4  // n_center (fixed by problem)

template <int H4C>
__global__ void __launch_bounds__(128) ll_fused_kernel(
    const float* __restrict__ x,
    const int* __restrict__ y,
    const float* __restrict__ mu_base,
    const float* __restrict__ cmu,
    const float* __restrict__ csig,
    const float* __restrict__ cpi,
    float* __restrict__ out,
    int H, int B)
{
    const int b    = blockIdx.x;
    const int tid  = threadIdx.x;
    const int lane = tid & 31;
    const int warp = tid >> 5;
    const int cls  = y[b];
    const float inv_g = 0.1f;  // 1 / GAMA

    const int H4 = (H4C > 0) ? H4C : (H >> 2);
    const float4* __restrict__ x4  = reinterpret_cast<const float4*>(x) + (size_t)b * H4;
    const float4* __restrict__ mb4 = reinterpret_cast<const float4*>(mu_base);
    const float4* __restrict__ mu0 = reinterpret_cast<const float4*>(cmu)  + (size_t)cls * KC * H4;
    const float4* __restrict__ sg0 = reinterpret_cast<const float4*>(csig) + (size_t)cls * KC * H4;

    float acc[KC];
#pragma unroll
    for (int k = 0; k < KC; ++k) acc[k] = 0.0f;

#pragma unroll
    for (int i0 = 0; i0 < ((H4C > 0) ? H4C : 1); i0 += 128) {
        // generic fallback path loops; specialized path fully unrolls (1 trip for H4C=128)
        int i = (H4C > 0) ? (i0 + tid) : 0;
        for (; i < H4; i += (H4C > 0) ? (H4C + 1) /*once*/ : 128) {
            if (H4C <= 0) { /* strided index for generic path */ }
            float4 xv = x4[i];
            float4 mv = mb4[i];
            float xs0 = (xv.x - mv.x) * inv_g;
            float xs1 = (xv.y - mv.y) * inv_g;
            float xs2 = (xv.z - mv.z) * inv_g;
            float xs3 = (xv.w - mv.w) * inv_g;
#pragma unroll
            for (int k = 0; k < KC; ++k) {
                float4 m = mu0[k * H4 + i];
                float4 s = sg0[k * H4 + i];
                float ds0 = (xs0 - m.x) * s.x;
                float ds1 = (xs1 - m.y) * s.y;
                float ds2 = (xs2 - m.z) * s.z;
                float ds3 = (xs3 - m.w) * s.w;
                float q = ds0 * ds0;
                q = fmaf(ds1, ds1, q);
                q = fmaf(ds2, ds2, q);
                q = fmaf(ds3, ds3, q);
                float p = (s.x * s.y) * (s.z * s.w);  // log-det via one log of product
                acc[k] += __logf(p) - 0.5f * q;
            }
            if (H4C > 0) break;
        }
    }

    // Warp butterfly reduction of the 4 per-center partial sums.
#pragma unroll
    for (int o = 16; o > 0; o >>= 1) {
#pragma unroll
        for (int k = 0; k < KC; ++k)
            acc[k] += __shfl_xor_sync(0xFFFFFFFFu, acc[k], o);
    }

    __shared__ float sp[4][KC];
    __shared__ bool s_last;
    if (lane == 0) {
#pragma unroll
        for (int k = 0; k < KC; ++k) sp[warp][k] = acc[k];
    }
    __syncthreads();

    if (tid == 0) {
        const int nw = blockDim.x >> 5;
        float tot[KC];
#pragma unroll
        for (int k = 0; k < KC; ++k) {
            float t = 0.0f;
            for (int w = 0; w < nw; ++w) t += sp[w][k];
            tot[k] = t;
        }
        // log-softmax over class_pi[cls, :]
        float pi[KC];
        float pmax = -CUDART_INF_F;
#pragma unroll
        for (int k = 0; k < KC; ++k) {
            pi[k] = cpi[cls * KC + k];
            pmax = fmaxf(pmax, pi[k]);
        }
        float se = 0.0f;
#pragma unroll
        for (int k = 0; k < KC; ++k) se += __expf(pi[k] - pmax);
        const float lse = __logf(se) + pmax;

        const float cst = -0.5f * (float)H * 1.8378770664093453f;  // log(2*pi)
        float best = -CUDART_INF_F;
#pragma unroll
        for (int k = 0; k < KC; ++k)
            best = fmaxf(best, tot[k] + cst + pi[k] - lse);
        g_ll[b] = best;

        __threadfence();
        unsigned int ticket = atomicAdd(&g_cnt, 1u);
        s_last = (ticket == (unsigned int)(gridDim.x - 1));
    }
    __syncthreads();

    if (s_last) {
        // Fixed-order tree reduction of B values with 128 threads.
        __shared__ float sr[128];
        float v = 0.0f;
        for (int i = tid; i < B; i += 128) v += g_ll[i];
        sr[tid] = v;
        __syncthreads();
#pragma unroll
        for (int o = 64; o > 32; o >>= 1) {
            if (tid < o) sr[tid] += sr[tid + o];
            __syncthreads();
        }
        if (tid < 32) {
            float w = sr[tid] + sr[tid + 32];
#pragma unroll
            for (int o = 16; o > 0; o >>= 1)
                w += __shfl_xor_sync(0xFFFFFFFFu, w, o);
            if (tid == 0) {
                out[0] = w / (float)B;
                g_cnt = 0;  // reset for next graph replay
            }
        }
    }
}

extern "C" void kernel_launch(void* const* d_in, const int* in_sizes, int n_in,
                              void* d_out, int out_size)
{
    const float* x   = (const float*)d_in[0];
    const int*   y   = (const int*)d_in[1];
    const float* mub = (const float*)d_in[2];
    const float* cmu = (const float*)d_in[3];
    const float* csg = (const float*)d_in[4];
    const float* cpi = (const float*)d_in[5];
    float*       out = (float*)d_out;

    const int B = in_sizes[1];  // batch (y elements)
    const int H = in_sizes[2];  // hidden (mu_base elements)

    if ((H >> 2) == 128) {
        ll_fused_kernel<128><<<B, 128>>>(x, y, mub, cmu, csg, cpi, out, H, B);
    } else {
        ll_fused_kernel<0><<<B, 128>>>(x, y, mub, cmu, csg, cpi, out, H, B);
    }
}